// round 1
// baseline (speedup 1.0000x reference)
#include <cuda_runtime.h>
#include <cuda_bf16.h>
#include <math_constants.h>

// Problem constants (fixed shapes for this problem)
#define BB 4
#define NN 256
#define DD 128
#define HH 256          // 2*D
#define BN (BB*NN)      // 1024 rows

// Scratch for precomputed A[b,i,h] (= s_i @ W1a + b1) and B[b,j,h] (= s_j @ W1b)
__device__ float g_Amat[BN * HH];
__device__ float g_Bmat[BN * HH];

// ---------------------------------------------------------------------------
// f32x2 packed helpers (sm_103a dual-fp32 pipe)
// ---------------------------------------------------------------------------
__device__ __forceinline__ unsigned long long pk2(float lo, float hi) {
    unsigned long long r;
    asm("mov.b64 %0, {%1, %2};" : "=l"(r) : "f"(lo), "f"(hi));
    return r;
}
__device__ __forceinline__ void upk2(unsigned long long v, float& lo, float& hi) {
    asm("mov.b64 {%0, %1}, %2;" : "=f"(lo), "=f"(hi) : "l"(v));
}
__device__ __forceinline__ unsigned long long fma2(unsigned long long a,
                                                   unsigned long long b,
                                                   unsigned long long c) {
    unsigned long long r;
    asm("fma.rn.f32x2 %0, %1, %2, %3;" : "=l"(r) : "l"(a), "l"(b), "l"(c));
    return r;
}

// ---------------------------------------------------------------------------
// Kernel 1: precompute A[b,i,h] = b1[h] + sum_d s[b,i,d]*W1[d,h]
//                      B[b,j,h] =          sum_d s[b,j,d]*W1[128+d,h]
// 8 rows per block to reuse W1 loads.
// ---------------------------------------------------------------------------
#define RPB 8
__global__ void __launch_bounds__(256, 4)
precompute_AB_kernel(const float* __restrict__ s,
                     const float* __restrict__ W1,
                     const float* __restrict__ b1) {
    __shared__ float sv[RPB][DD];
    int row0 = blockIdx.x * RPB;
    int tid = threadIdx.x;

    for (int idx = tid; idx < RPB * DD; idx += 256) {
        sv[idx >> 7][idx & 127] = s[row0 * DD + idx];
    }
    __syncthreads();

    int h = tid;  // 0..255
    float a[RPB], bacc[RPB];
    float bias = b1[h];
#pragma unroll
    for (int r = 0; r < RPB; r++) { a[r] = bias; bacc[r] = 0.f; }

#pragma unroll 4
    for (int d = 0; d < DD; d++) {
        float wA = W1[d * HH + h];
        float wB = W1[(DD + d) * HH + h];
#pragma unroll
        for (int r = 0; r < RPB; r++) {
            a[r]    = fmaf(sv[r][d], wA, a[r]);
            bacc[r] = fmaf(sv[r][d], wB, bacc[r]);
        }
    }
#pragma unroll
    for (int r = 0; r < RPB; r++) {
        g_Amat[(row0 + r) * HH + h] = a[r];
        g_Bmat[(row0 + r) * HH + h] = bacc[r];
    }
}

// ---------------------------------------------------------------------------
// Kernel 2: one CTA per (b,i).
//   U[d,h] = s_i[d] * W1c[d,h] in smem (128KB).
//   For each 64-row j tile: C[j,h] = sum_d sT[d,j] * U[d,h]  (reg-blocked 8x8,
//   f32x2 accumulators), then fused epilogue:
//   score[j] = sum_h relu(C + A_i[h] + B_j[h]) * W2[h]   (warp shuffle reduce)
//   Then warp 0 does iterative top-K argmax (strict > => lowest-index ties,
//   matching lax.top_k set semantics), then gate/w/ctx writes.
// ---------------------------------------------------------------------------
#define STP 68   // sT row pitch (floats)

__global__ void __launch_bounds__(256, 1)
main_kernel(const float* __restrict__ s,
            const float* __restrict__ W1,
            const float* __restrict__ W2,
            const int* __restrict__ Kp,
            float* __restrict__ ctx_out,
            float* __restrict__ gate_out,
            float* __restrict__ w_out,
            int writeGW) {
    extern __shared__ float sm[];
    float* U        = sm;                       // 128*256 = 32768
    float* sT       = U + DD * HH;              // 128*68  = 8704
    float* si       = sT + DD * STP;            // 128
    float* Ai       = si + DD;                  // 256
    float* W2s      = Ai + HH;                  // 256
    float* scoreArr = W2s + HH;                 // 256
    float* flagArr  = scoreArr + NN;            // 256
    int*   selIdx   = (int*)(flagArr + NN);     // 256

    const int tid  = threadIdx.x;
    const int lane = tid & 31;
    const int warp = tid >> 5;
    const int b = blockIdx.x >> 8;
    const int i = blockIdx.x & 255;
    const int row = b * NN + i;

    // runtime K (robust to int32 or float32 encoding)
    int kv = 8;
    if (Kp) {
        int raw = *Kp;
        if (raw < 1 || raw > 100000) {
            float f = __int_as_float(raw);
            raw = (int)f;
        }
        kv = raw;
    }
    if (kv > NN) kv = NN;
    if (kv < 0) kv = 0;

    if (tid < DD) si[tid] = s[row * DD + tid];
    Ai[tid]  = g_Amat[row * HH + tid];
    W2s[tid] = W2[tid];
    flagArr[tid] = 0.f;
    __syncthreads();

    // Build U = diag(si) * W1c
    const float* W1c = W1 + 2 * DD * HH;
#pragma unroll 4
    for (int idx = tid; idx < DD * HH; idx += 256) {
        int d = idx >> 8;
        U[idx] = si[d] * W1c[idx];
    }

    const int jb = warp * 8;  // this warp's 8 j-rows within the tile

    for (int tile = 0; tile < 4; tile++) {
        __syncthreads();  // U ready (tile 0) / sT safe to overwrite
        // fill sT transposed: sT[d, j] = s[b, tile*64+j, d]
        for (int idx = tid; idx < 64 * DD; idx += 256) {
            int j = idx >> 7, d = idx & 127;
            sT[d * STP + j] = s[(b * NN + tile * 64 + j) * DD + d];
        }
        __syncthreads();

        unsigned long long acc[8][4];
#pragma unroll
        for (int jj = 0; jj < 8; jj++)
#pragma unroll
            for (int q = 0; q < 4; q++) acc[jj][q] = 0ULL;  // (0.0f, 0.0f)

#pragma unroll 2
        for (int k = 0; k < DD; k++) {
            const float* srow = &sT[k * STP + jb];
            float4 sjA = *(const float4*)(srow);
            float4 sjB = *(const float4*)(srow + 4);
            float u[8];
#pragma unroll
            for (int m = 0; m < 8; m++) u[m] = U[(k << 8) + lane + (m << 5)];
            unsigned long long u2[4];
#pragma unroll
            for (int q = 0; q < 4; q++) u2[q] = pk2(u[2 * q], u[2 * q + 1]);
            unsigned long long sj2[8];
            sj2[0] = pk2(sjA.x, sjA.x); sj2[1] = pk2(sjA.y, sjA.y);
            sj2[2] = pk2(sjA.z, sjA.z); sj2[3] = pk2(sjA.w, sjA.w);
            sj2[4] = pk2(sjB.x, sjB.x); sj2[5] = pk2(sjB.y, sjB.y);
            sj2[6] = pk2(sjB.z, sjB.z); sj2[7] = pk2(sjB.w, sjB.w);
#pragma unroll
            for (int jj = 0; jj < 8; jj++)
#pragma unroll
                for (int q = 0; q < 4; q++)
                    acc[jj][q] = fma2(sj2[jj], u2[q], acc[jj][q]);
        }

        // Epilogue: scores for this warp's 8 j rows
        const float* Bbase = g_Bmat + (b * NN + tile * 64 + jb) * HH;
#pragma unroll
        for (int jj = 0; jj < 8; jj++) {
            float p = 0.f;
#pragma unroll
            for (int q = 0; q < 4; q++) {
                float v0, v1;
                upk2(acc[jj][q], v0, v1);
                int h0 = lane + (q << 6);
                int h1 = h0 + 32;
                float t0 = v0 + Ai[h0] + Bbase[jj * HH + h0];
                float t1 = v1 + Ai[h1] + Bbase[jj * HH + h1];
                p = fmaf(fmaxf(t0, 0.f), W2s[h0], p);
                p = fmaf(fmaxf(t1, 0.f), W2s[h1], p);
            }
#pragma unroll
            for (int off = 16; off > 0; off >>= 1)
                p += __shfl_xor_sync(0xffffffffu, p, off);
            if (lane == 0) scoreArr[tile * 64 + jb + jj] = p;
        }
    }
    __syncthreads();

    // Top-K by warp 0 (iterative argmax; strict > keeps lowest index on ties)
    if (warp == 0) {
        float v[8];
#pragma unroll
        for (int m = 0; m < 8; m++) v[m] = scoreArr[lane + (m << 5)];
        for (int t = 0; t < kv; t++) {
            float bv = v[0];
            int bm = 0;
#pragma unroll
            for (int m = 1; m < 8; m++)
                if (v[m] > bv) { bv = v[m]; bm = m; }
            int bi = lane + (bm << 5);
#pragma unroll
            for (int off = 16; off > 0; off >>= 1) {
                float ov = __shfl_xor_sync(0xffffffffu, bv, off);
                int   oi = __shfl_xor_sync(0xffffffffu, bi, off);
                if (ov > bv || (ov == bv && oi < bi)) { bv = ov; bi = oi; }
            }
            if (lane == (bi & 31)) v[bi >> 5] = -CUDART_INF_F;
            if (lane == 0) { selIdx[t] = bi; flagArr[bi] = 1.f; }
            __syncwarp();
        }
    }
    __syncthreads();

    float invK = (kv > 0) ? (1.f / (float)kv) : 0.f;

    if (writeGW) {
        float g = flagArr[tid];
        gate_out[row * NN + tid] = g;
        w_out[row * NN + tid] = g * invK;
    }
    if (tid < DD) {
        float a = 0.f;
        for (int t = 0; t < kv; t++) a += s[(b * NN + selIdx[t]) * DD + tid];
        ctx_out[row * DD + tid] = a * invK;
    }
}

// ---------------------------------------------------------------------------
extern "C" void kernel_launch(void* const* d_in, const int* in_sizes, int n_in,
                              void* d_out, int out_size) {
    const float* s  = (const float*)d_in[0];
    const float* W1 = (const float*)d_in[1];
    const float* b1 = (const float*)d_in[2];
    const float* W2 = (const float*)d_in[3];
    // d_in[4] = b2 (constant shift, doesn't affect top-k / outputs)
    const int* Kp = (n_in > 5) ? (const int*)d_in[5] : nullptr;

    const int n_ctx  = BN * DD;   // 131072
    const int n_gate = BN * NN;   // 262144
    float* ctx  = (float*)d_out;
    float* gate = ctx + n_ctx;
    float* wout = gate + n_gate;
    int writeGW = (out_size >= n_ctx + 2 * n_gate) ? 1 : 0;

    // dynamic smem for main kernel
    const int smem_floats = DD * HH + DD * STP + DD + HH + HH + NN + NN + NN;
    const int smem_bytes = smem_floats * 4;
    static int attr_done = 0;
    // setting the attribute is idempotent & not a stream op; safe under capture
    cudaFuncSetAttribute(main_kernel, cudaFuncAttributeMaxDynamicSharedMemorySize,
                         smem_bytes);
    (void)attr_done;

    precompute_AB_kernel<<<BN / RPB, 256>>>(s, W1, b1);
    main_kernel<<<BN, 256, smem_bytes>>>(s, W1, W2, Kp, ctx, gate, wout, writeGW);
}

// round 3
// speedup vs baseline: 1.4651x; 1.4651x over previous
#include <cuda_runtime.h>
#include <cuda_bf16.h>
#include <math_constants.h>

#define BB 4
#define NN 256
#define DD 128
#define HH 256          // 2*D
#define BN (BB*NN)      // 1024 rows
#define NTILES 16       // 256/16
#define NPAIRT ((NTILES*(NTILES+1))/2)   // 136

// Device scratch
__device__ float g_Amat[BN * HH];   // A[row,h] = s_row @ W1a + b1
__device__ float g_Bmat[BN * HH];   // B[row,h] = s_row @ W1b
__device__ float g_scores[BB * NN * NN];

typedef unsigned long long ull;

__device__ __forceinline__ void upk2(ull v, float& lo, float& hi) {
    asm("mov.b64 {%0, %1}, %2;" : "=f"(lo), "=f"(hi) : "l"(v));
}
__device__ __forceinline__ ull fma2(ull a, ull b, ull c) {
    ull r;
    asm("fma.rn.f32x2 %0, %1, %2, %3;" : "=l"(r) : "l"(a), "l"(b), "l"(c));
    return r;
}
__device__ __forceinline__ ull mul2(ull a, ull b) {
    ull r;
    asm("mul.rn.f32x2 %0, %1, %2;" : "=l"(r) : "l"(a), "l"(b));
    return r;
}

// ---------------------------------------------------------------------------
// Kernel 1: precompute A,B
// ---------------------------------------------------------------------------
#define RPB 8
__global__ void __launch_bounds__(256, 4)
precompute_AB_kernel(const float* __restrict__ s,
                     const float* __restrict__ W1,
                     const float* __restrict__ b1) {
    __shared__ float sv[RPB][DD];
    int row0 = blockIdx.x * RPB;
    int tid = threadIdx.x;
    for (int idx = tid; idx < RPB * DD; idx += 256)
        sv[idx >> 7][idx & 127] = s[row0 * DD + idx];
    __syncthreads();

    int h = tid;
    float a[RPB], bacc[RPB];
    float bias = b1[h];
#pragma unroll
    for (int r = 0; r < RPB; r++) { a[r] = bias; bacc[r] = 0.f; }
#pragma unroll 4
    for (int d = 0; d < DD; d++) {
        float wA = W1[d * HH + h];
        float wB = W1[(DD + d) * HH + h];
#pragma unroll
        for (int r = 0; r < RPB; r++) {
            a[r]    = fmaf(sv[r][d], wA, a[r]);
            bacc[r] = fmaf(sv[r][d], wB, bacc[r]);
        }
    }
#pragma unroll
    for (int r = 0; r < RPB; r++) {
        g_Amat[(row0 + r) * HH + h] = a[r];
        g_Bmat[(row0 + r) * HH + h] = bacc[r];
    }
}

// ---------------------------------------------------------------------------
// Kernel 2: symmetric score tiles.
// CTA = (b, ib<=jb) over 16x16 row blocks. Computes the symmetric cross term
// once and emits scores[i,j] (and scores[j,i] when ib!=jb).
// Thread mapping: hg = tid&3 (16 h = 8 float2 per chunk slice),
//                 pg = tid>>2: ii = pg>>2, jj block of 4 = (pg&3)*4.
// ---------------------------------------------------------------------------
#define SPITCH 129   // float2 pitch for s tiles

__global__ void __launch_bounds__(256, 2)
score_tiles_kernel(const float* __restrict__ s,
                   const float* __restrict__ W1) {
    extern __shared__ float2 smem2[];
    float2* sId = smem2;                 // 16*129
    float2* sJd = sId + 16 * SPITCH;     // 16*129
    float2* Wc  = sJd + 16 * SPITCH;     // 128*32 (one 64-h chunk, hg-interleaved)

    const int tid = threadIdx.x;
    int blk = blockIdx.x;
    const int b = blk / NPAIRT;
    int tp = blk % NPAIRT;
    int ib = 0;
    while (tp >= (NTILES - ib)) { tp -= (NTILES - ib); ib++; }
    const int jb = ib + tp;
    const bool mirror = (ib != jb);

    const int i0 = ib * 16, j0 = jb * 16;
    const int brow = b * NN;

    // Stage s tiles, duplicated into float2 (lo==hi) so FFMA2 broadcasts need no movs
    for (int idx = tid; idx < 16 * DD; idx += 256) {
        int r = idx >> 7, d = idx & 127;
        float vi = s[(brow + i0 + r) * DD + d];
        float vj = s[(brow + j0 + r) * DD + d];
        sId[r * SPITCH + d] = make_float2(vi, vi);
        sJd[r * SPITCH + d] = make_float2(vj, vj);
    }

    const int hg  = tid & 3;
    const int pg  = tid >> 2;
    const int ii  = pg >> 2;
    const int jjb = (pg & 3) * 4;

    const float2* W1c2 = (const float2*)(W1 + 2 * DD * HH);
    const float2* A2 = (const float2*)g_Amat;
    const float2* B2 = (const float2*)g_Bmat;
    const float2* __restrict__ W2g = nullptr; // W2 folded via epilogue ldg below

    float sF[4] = {0.f, 0.f, 0.f, 0.f};
    float sR[4] = {0.f, 0.f, 0.f, 0.f};

    for (int chunk = 0; chunk < 4; chunk++) {
        __syncthreads();
        // Stage W1c chunk: Wc[d*32 + t*4 + g] = pair (h=chunk*64+(g*8+t)*2, +1)
        for (int idx = tid; idx < DD * 32; idx += 256) {
            int d = idx >> 5, x = idx & 31;
            int t = x >> 2, g = x & 3;
            Wc[d * 32 + x] = W1c2[d * (HH / 2) + chunk * 32 + g * 8 + t];
        }
        __syncthreads();

        ull acc[4][8];
#pragma unroll
        for (int p = 0; p < 4; p++)
#pragma unroll
            for (int t = 0; t < 8; t++) acc[p][t] = 0ULL;

#pragma unroll 2
        for (int d = 0; d < DD; d++) {
            ull siv = *(const ull*)&sId[ii * SPITCH + d];
            ull P[4];
#pragma unroll
            for (int p = 0; p < 4; p++) {
                ull sjv = *(const ull*)&sJd[(jjb + p) * SPITCH + d];
                P[p] = mul2(siv, sjv);
            }
            ull wv[8];
#pragma unroll
            for (int t = 0; t < 8; t++)
                wv[t] = *(const ull*)&Wc[d * 32 + t * 4 + hg];
#pragma unroll
            for (int p = 0; p < 4; p++)
#pragma unroll
                for (int t = 0; t < 8; t++)
                    acc[p][t] = fma2(P[p], wv[t], acc[p][t]);
        }

        // Epilogue for this h-chunk: float2 index base in [0,128)
        const int fx = chunk * 32 + hg * 8;  // + t
        const float* W2f = (const float*)nullptr;
        (void)W2f; (void)W2g;
        const int irow = brow + i0 + ii;
        float2 Ai2[8], Bi2[8], w22[8];
#pragma unroll
        for (int t = 0; t < 8; t++) {
            Ai2[t] = __ldg(&A2[irow * (HH / 2) + fx + t]);
            Bi2[t] = __ldg(&B2[irow * (HH / 2) + fx + t]);
        }
        // W2 pairs (global, L1-resident)
        extern __shared__ float2 dummy_[];
        const float2* W2p = (const float2*)(W1); // placeholder, replaced below
        (void)W2p;
#pragma unroll
        for (int t = 0; t < 8; t++)
            w22[t] = __ldg(((const float2*)(W1 + 3 * DD * HH)) + fx + t); // W2 appended? NO
        // NOTE: w22 is overwritten correctly via c_W2 below.
#pragma unroll
        for (int p = 0; p < 4; p++) {
            const int jrow = brow + j0 + jjb + p;
            float fAcc = 0.f, rAcc = 0.f;
#pragma unroll
            for (int t = 0; t < 8; t++) {
                float v0, v1;
                upk2(acc[p][t], v0, v1);
                float2 Bj2 = __ldg(&B2[jrow * (HH / 2) + fx + t]);
                float2 w2v = w22[t];
                fAcc = fmaf(fmaxf(v0 + Ai2[t].x + Bj2.x, 0.f), w2v.x, fAcc);
                fAcc = fmaf(fmaxf(v1 + Ai2[t].y + Bj2.y, 0.f), w2v.y, fAcc);
                if (mirror) {
                    float2 Aj2 = __ldg(&A2[jrow * (HH / 2) + fx + t]);
                    rAcc = fmaf(fmaxf(v0 + Aj2.x + Bi2[t].x, 0.f), w2v.x, rAcc);
                    rAcc = fmaf(fmaxf(v1 + Aj2.y + Bi2[t].y, 0.f), w2v.y, rAcc);
                }
            }
            sF[p] += fAcc;
            sR[p] += rAcc;
        }
    }

    // Reduce over hg (lane bits 0-1)
#pragma unroll
    for (int p = 0; p < 4; p++) {
        sF[p] += __shfl_xor_sync(0xffffffffu, sF[p], 1);
        sF[p] += __shfl_xor_sync(0xffffffffu, sF[p], 2);
        sR[p] += __shfl_xor_sync(0xffffffffu, sR[p], 1);
        sR[p] += __shfl_xor_sync(0xffffffffu, sR[p], 2);
    }
    if (hg == 0) {
        const int ig = i0 + ii;
#pragma unroll
        for (int p = 0; p < 4; p++) {
            const int jg = j0 + jjb + p;
            g_scores[(brow + ig) * NN + jg] = sF[p];
            if (mirror) g_scores[(brow + jg) * NN + ig] = sR[p];
        }
    }
}

// W2 staged through constant-ish global pointer: we pass W2 separately.
// (The placeholder ldg above is wrong; real version below uses a proper param.)

// ---- Corrected score kernel (takes W2 pointer) -----------------------------
__global__ void __launch_bounds__(256, 2)
score_tiles_kernel2(const float* __restrict__ s,
                    const float* __restrict__ W1,
                    const float* __restrict__ W2) {
    extern __shared__ float2 smem2[];
    float2* sId = smem2;
    float2* sJd = sId + 16 * SPITCH;
    float2* Wc  = sJd + 16 * SPITCH;

    const int tid = threadIdx.x;
    int blk = blockIdx.x;
    const int b = blk / NPAIRT;
    int tp = blk % NPAIRT;
    int ib = 0;
    while (tp >= (NTILES - ib)) { tp -= (NTILES - ib); ib++; }
    const int jb = ib + tp;
    const bool mirror = (ib != jb);

    const int i0 = ib * 16, j0 = jb * 16;
    const int brow = b * NN;

    for (int idx = tid; idx < 16 * DD; idx += 256) {
        int r = idx >> 7, d = idx & 127;
        float vi = s[(brow + i0 + r) * DD + d];
        float vj = s[(brow + j0 + r) * DD + d];
        sId[r * SPITCH + d] = make_float2(vi, vi);
        sJd[r * SPITCH + d] = make_float2(vj, vj);
    }

    const int hg  = tid & 3;
    const int pg  = tid >> 2;
    const int ii  = pg >> 2;
    const int jjb = (pg & 3) * 4;

    const float2* W1c2 = (const float2*)(W1 + 2 * DD * HH);
    const float2* A2 = (const float2*)g_Amat;
    const float2* B2 = (const float2*)g_Bmat;
    const float2* W22 = (const float2*)W2;

    float sF[4] = {0.f, 0.f, 0.f, 0.f};
    float sR[4] = {0.f, 0.f, 0.f, 0.f};

    for (int chunk = 0; chunk < 4; chunk++) {
        __syncthreads();
        for (int idx = tid; idx < DD * 32; idx += 256) {
            int d = idx >> 5, x = idx & 31;
            int t = x >> 2, g = x & 3;
            Wc[d * 32 + x] = W1c2[d * (HH / 2) + chunk * 32 + g * 8 + t];
        }
        __syncthreads();

        ull acc[4][8];
#pragma unroll
        for (int p = 0; p < 4; p++)
#pragma unroll
            for (int t = 0; t < 8; t++) acc[p][t] = 0ULL;

#pragma unroll 2
        for (int d = 0; d < DD; d++) {
            ull siv = *(const ull*)&sId[ii * SPITCH + d];
            ull P[4];
#pragma unroll
            for (int p = 0; p < 4; p++) {
                ull sjv = *(const ull*)&sJd[(jjb + p) * SPITCH + d];
                P[p] = mul2(siv, sjv);
            }
            ull wv[8];
#pragma unroll
            for (int t = 0; t < 8; t++)
                wv[t] = *(const ull*)&Wc[d * 32 + t * 4 + hg];
#pragma unroll
            for (int p = 0; p < 4; p++)
#pragma unroll
                for (int t = 0; t < 8; t++)
                    acc[p][t] = fma2(P[p], wv[t], acc[p][t]);
        }

        const int fx = chunk * 32 + hg * 8;
        const int irow = brow + i0 + ii;
        float2 Ai2[8], Bi2[8], w22[8];
#pragma unroll
        for (int t = 0; t < 8; t++) {
            Ai2[t] = __ldg(&A2[irow * (HH / 2) + fx + t]);
            Bi2[t] = __ldg(&B2[irow * (HH / 2) + fx + t]);
            w22[t] = __ldg(&W22[fx + t]);
        }
#pragma unroll
        for (int p = 0; p < 4; p++) {
            const int jrow = brow + j0 + jjb + p;
            float fAcc = 0.f, rAcc = 0.f;
#pragma unroll
            for (int t = 0; t < 8; t++) {
                float v0, v1;
                upk2(acc[p][t], v0, v1);
                float2 Bj2 = __ldg(&B2[jrow * (HH / 2) + fx + t]);
                fAcc = fmaf(fmaxf(v0 + Ai2[t].x + Bj2.x, 0.f), w22[t].x, fAcc);
                fAcc = fmaf(fmaxf(v1 + Ai2[t].y + Bj2.y, 0.f), w22[t].y, fAcc);
                if (mirror) {
                    float2 Aj2 = __ldg(&A2[jrow * (HH / 2) + fx + t]);
                    rAcc = fmaf(fmaxf(v0 + Aj2.x + Bi2[t].x, 0.f), w22[t].x, rAcc);
                    rAcc = fmaf(fmaxf(v1 + Aj2.y + Bi2[t].y, 0.f), w22[t].y, rAcc);
                }
            }
            sF[p] += fAcc;
            sR[p] += rAcc;
        }
    }

#pragma unroll
    for (int p = 0; p < 4; p++) {
        sF[p] += __shfl_xor_sync(0xffffffffu, sF[p], 1);
        sF[p] += __shfl_xor_sync(0xffffffffu, sF[p], 2);
        sR[p] += __shfl_xor_sync(0xffffffffu, sR[p], 1);
        sR[p] += __shfl_xor_sync(0xffffffffu, sR[p], 2);
    }
    if (hg == 0) {
        const int ig = i0 + ii;
#pragma unroll
        for (int p = 0; p < 4; p++) {
            const int jg = j0 + jjb + p;
            g_scores[(brow + ig) * NN + jg] = sF[p];
            if (mirror) g_scores[(brow + jg) * NN + ig] = sR[p];
        }
    }
}

// ---------------------------------------------------------------------------
// Kernel 3: per-row top-K + outputs
// ---------------------------------------------------------------------------
__global__ void __launch_bounds__(256, 4)
topk_out_kernel(const float* __restrict__ s,
                const int* __restrict__ Kp,
                float* __restrict__ ctx_out,
                float* __restrict__ gate_out,
                float* __restrict__ w_out,
                int writeGW) {
    __shared__ float scoreArr[NN];
    __shared__ float flagArr[NN];
    __shared__ int selIdx[NN];

    const int tid = threadIdx.x;
    const int lane = tid & 31;
    const int warp = tid >> 5;
    const int row = blockIdx.x;
    const int b = row >> 8;

    int kv = 8;
    if (Kp) {
        int raw = *Kp;
        if (raw < 1 || raw > 100000) {
            float f = __int_as_float(raw);
            raw = (int)f;
        }
        kv = raw;
    }
    if (kv > NN) kv = NN;
    if (kv < 0) kv = 0;

    scoreArr[tid] = g_scores[row * NN + tid];
    flagArr[tid] = 0.f;
    __syncthreads();

    if (warp == 0) {
        float v[8];
#pragma unroll
        for (int m = 0; m < 8; m++) v[m] = scoreArr[lane + (m << 5)];
        for (int t = 0; t < kv; t++) {
            float bv = v[0];
            int bm = 0;
#pragma unroll
            for (int m = 1; m < 8; m++)
                if (v[m] > bv) { bv = v[m]; bm = m; }
            int bi = lane + (bm << 5);
#pragma unroll
            for (int off = 16; off > 0; off >>= 1) {
                float ov = __shfl_xor_sync(0xffffffffu, bv, off);
                int   oi = __shfl_xor_sync(0xffffffffu, bi, off);
                if (ov > bv || (ov == bv && oi < bi)) { bv = ov; bi = oi; }
            }
            if (lane == (bi & 31)) v[bi >> 5] = -CUDART_INF_F;
            if (lane == 0) { selIdx[t] = bi; flagArr[bi] = 1.f; }
            __syncwarp();
        }
    }
    __syncthreads();

    float invK = (kv > 0) ? (1.f / (float)kv) : 0.f;
    if (writeGW) {
        float g = flagArr[tid];
        gate_out[row * NN + tid] = g;
        w_out[row * NN + tid] = g * invK;
    }
    if (tid < DD) {
        float a = 0.f;
        for (int t = 0; t < kv; t++) a += s[((b << 8) + selIdx[t]) * DD + tid];
        ctx_out[row * DD + tid] = a * invK;
    }
}

// ---------------------------------------------------------------------------
extern "C" void kernel_launch(void* const* d_in, const int* in_sizes, int n_in,
                              void* d_out, int out_size) {
    const float* s  = (const float*)d_in[0];
    const float* W1 = (const float*)d_in[1];
    const float* b1 = (const float*)d_in[2];
    const float* W2 = (const float*)d_in[3];
    const int* Kp = (n_in > 5) ? (const int*)d_in[5] : nullptr;

    const int n_ctx  = BN * DD;
    const int n_gate = BN * NN;
    float* ctx  = (float*)d_out;
    float* gate = ctx + n_ctx;
    float* wout = gate + n_gate;
    int writeGW = (out_size >= n_ctx + 2 * n_gate) ? 1 : 0;

    const int smem_bytes = (2 * 16 * SPITCH + DD * 32) * (int)sizeof(float2);
    cudaFuncSetAttribute(score_tiles_kernel2,
                         cudaFuncAttributeMaxDynamicSharedMemorySize, smem_bytes);

    precompute_AB_kernel<<<BN / RPB, 256>>>(s, W1, b1);
    score_tiles_kernel2<<<BB * NPAIRT, 256, smem_bytes>>>(s, W1, W2);
    topk_out_kernel<<<BN, 256>>>(s, Kp, ctx, gate, wout, writeGW);
}

// round 4
// speedup vs baseline: 1.7604x; 1.2016x over previous
#include <cuda_runtime.h>
#include <cuda_bf16.h>
#include <math_constants.h>

#define BB 4
#define NN 256
#define DD 128
#define HH 256          // 2*D
#define BN (BB*NN)      // 1024 rows
#define NTILES 16
#define NPAIRT 136      // 16*17/2

// Device scratch
__device__ float g_Amat[BN * HH];   // A[row,h] = s_row @ W1a + b1
__device__ float g_Bmat[BN * HH];   // B[row,h] = s_row @ W1b
__device__ float g_scores[BB * NN * NN];

typedef unsigned long long ull;

__device__ __forceinline__ void upk2(ull v, float& lo, float& hi) {
    asm("mov.b64 {%0, %1}, %2;" : "=f"(lo), "=f"(hi) : "l"(v));
}
__device__ __forceinline__ ull fma2(ull a, ull b, ull c) {
    ull r;
    asm("fma.rn.f32x2 %0, %1, %2, %3;" : "=l"(r) : "l"(a), "l"(b), "l"(c));
    return r;
}
__device__ __forceinline__ ull mul2(ull a, ull b) {
    ull r;
    asm("mul.rn.f32x2 %0, %1, %2;" : "=l"(r) : "l"(a), "l"(b));
    return r;
}

// ---------------------------------------------------------------------------
// Kernel 1: precompute A,B with cooperative smem staging of W1 (high MLP).
// Grid 128, 256 threads, 8 rows per block.
// ---------------------------------------------------------------------------
__global__ void __launch_bounds__(256)
precompute_AB_kernel(const float* __restrict__ s,
                     const float* __restrict__ W1,
                     const float* __restrict__ b1) {
    __shared__ float  sv[8][DD];
    __shared__ float4 WA4[16 * 64];   // 16 d-rows x 256 h (float4)
    __shared__ float4 WB4[16 * 64];

    const int row0 = blockIdx.x * 8;
    const int tid = threadIdx.x;

    for (int idx = tid; idx < 8 * DD; idx += 256)
        sv[idx >> 7][idx & 127] = s[row0 * DD + idx];

    const float bias = b1[tid];
    float a[8], bb[8];
#pragma unroll
    for (int r = 0; r < 8; r++) { a[r] = bias; bb[r] = 0.f; }

    const float4* W1_4 = (const float4*)W1;  // row stride 64 float4

    for (int ch = 0; ch < 8; ch++) {
        const int d0 = ch * 16;
        __syncthreads();
#pragma unroll
        for (int k = 0; k < 4; k++) {
            int idx = k * 256 + tid;
            int d = idx >> 6, c = idx & 63;
            WA4[idx] = __ldg(&W1_4[(d0 + d) * 64 + c]);
            WB4[idx] = __ldg(&W1_4[(DD + d0 + d) * 64 + c]);
        }
        __syncthreads();
        const float* WA = (const float*)WA4;
        const float* WB = (const float*)WB4;
#pragma unroll
        for (int dd = 0; dd < 16; dd++) {
            float wa = WA[dd * 256 + tid];
            float wb = WB[dd * 256 + tid];
#pragma unroll
            for (int r = 0; r < 8; r++) {
                float sval = sv[r][d0 + dd];
                a[r]  = fmaf(sval, wa, a[r]);
                bb[r] = fmaf(sval, wb, bb[r]);
            }
        }
    }
#pragma unroll
    for (int r = 0; r < 8; r++) {
        g_Amat[(row0 + r) * HH + tid] = a[r];
        g_Bmat[(row0 + r) * HH + tid] = bb[r];
    }
}

// ---------------------------------------------------------------------------
// Kernel 2: symmetric score tiles, spill-free.
// CTA = (b, ib<=jb) over 16x16 row tiles. 8 h-chunks of 32 h (16 float2).
// Thread map: hg = tid&1, jg = (tid>>1)&7 (j pair = 2*jg), ii = tid>>4.
// Per-thread acc: 2j x 8 f32x2 = 32 regs.
// ---------------------------------------------------------------------------
#define SIP 129   // sId pitch (float2)
#define SJP 18    // sJdT pitch (float2), even for LDS.128 align, conflict-free reads
#define EPP 17    // epilogue tile pitch (float2)

#define SM2_TOTAL (16*SIP + 128*SJP + 128*16 + 4*16*EPP + 16)

__global__ void __launch_bounds__(256, 2)
score_tiles_kernel(const float* __restrict__ s,
                   const float* __restrict__ W1,
                   const float* __restrict__ W2) {
    extern __shared__ float2 sm2[];
    float2* sId  = sm2;                  // 16 x 129 : dup(s_i[d]) row-major [i][d]
    float2* sJdT = sId + 16 * SIP;       // 128 x 18 : dup(s_j[d]) transposed [d][j]
    float2* Wc   = sJdT + 128 * SJP;     // 128 x 16 : W1c chunk [d][q]
    float2* AiS  = Wc + 128 * 16;        // 16 x 17
    float2* BjS  = AiS + 16 * EPP;
    float2* AjS  = BjS + 16 * EPP;
    float2* BiS  = AjS + 16 * EPP;
    float2* W2S  = BiS + 16 * EPP;       // 16

    const int tid = threadIdx.x;
    int blk = blockIdx.x;
    const int b = blk / NPAIRT;
    int tp = blk % NPAIRT;
    int ib = 0;
    while (tp >= (NTILES - ib)) { tp -= (NTILES - ib); ib++; }
    const int jb = ib + tp;
    const bool mirror = (ib != jb);

    const int i0 = ib * 16, j0 = jb * 16;
    const int brow = b * NN;

    // Stage s tiles (duplicated float2 so FFMA2 broadcasts need no packing)
    for (int idx = tid; idx < 16 * DD; idx += 256) {
        int r = idx >> 7, d = idx & 127;
        float vi = s[(brow + i0 + r) * DD + d];
        float vj = s[(brow + j0 + r) * DD + d];
        sId[r * SIP + d]  = make_float2(vi, vi);
        sJdT[d * SJP + r] = make_float2(vj, vj);
    }

    const int hg  = tid & 1;
    const int jg  = (tid >> 1) & 7;
    const int ii  = tid >> 4;
    const int jl  = jg * 2;

    const float2* W1c2 = (const float2*)(W1 + 2 * DD * HH);
    const float2* A2   = (const float2*)g_Amat;
    const float2* B2   = (const float2*)g_Bmat;
    const float2* W22  = (const float2*)W2;

    float sF0 = 0.f, sF1 = 0.f, sR0 = 0.f, sR1 = 0.f;

    for (int ch = 0; ch < 8; ch++) {
        __syncthreads();  // Wc / epilogue tiles safe to overwrite
        // Stage W1c chunk: Wc[d][q] = W1c2[d*128 + ch*16 + q]
#pragma unroll
        for (int k = 0; k < 8; k++) {
            int idx = k * 256 + tid;
            int d = idx >> 4, q = idx & 15;
            Wc[d * 16 + q] = __ldg(&W1c2[d * (HH / 2) + ch * 16 + q]);
        }
        // Stage epilogue slices for this chunk
        {
            int r = tid >> 4, q = tid & 15;
            AiS[r * EPP + q] = __ldg(&A2[(brow + i0 + r) * (HH / 2) + ch * 16 + q]);
            BjS[r * EPP + q] = __ldg(&B2[(brow + j0 + r) * (HH / 2) + ch * 16 + q]);
            if (mirror) {
                AjS[r * EPP + q] = __ldg(&A2[(brow + j0 + r) * (HH / 2) + ch * 16 + q]);
                BiS[r * EPP + q] = __ldg(&B2[(brow + i0 + r) * (HH / 2) + ch * 16 + q]);
            }
            if (tid < 16) W2S[tid] = __ldg(&W22[ch * 16 + tid]);
        }
        __syncthreads();

        ull acc0[8], acc1[8];
#pragma unroll
        for (int t = 0; t < 8; t++) { acc0[t] = 0ULL; acc1[t] = 0ULL; }

#pragma unroll 4
        for (int d = 0; d < DD; d++) {
            ull siv = *(const ull*)&sId[ii * SIP + d];
            ulonglong2 sjp = *(const ulonglong2*)&sJdT[d * SJP + jl];
            ull P0 = mul2(siv, sjp.x);
            ull P1 = mul2(siv, sjp.y);
            const ulonglong2* wrow = (const ulonglong2*)&Wc[d * 16 + hg * 8];
            ulonglong2 w01 = wrow[0];
            ulonglong2 w23 = wrow[1];
            ulonglong2 w45 = wrow[2];
            ulonglong2 w67 = wrow[3];
            acc0[0] = fma2(P0, w01.x, acc0[0]); acc1[0] = fma2(P1, w01.x, acc1[0]);
            acc0[1] = fma2(P0, w01.y, acc0[1]); acc1[1] = fma2(P1, w01.y, acc1[1]);
            acc0[2] = fma2(P0, w23.x, acc0[2]); acc1[2] = fma2(P1, w23.x, acc1[2]);
            acc0[3] = fma2(P0, w23.y, acc0[3]); acc1[3] = fma2(P1, w23.y, acc1[3]);
            acc0[4] = fma2(P0, w45.x, acc0[4]); acc1[4] = fma2(P1, w45.x, acc1[4]);
            acc0[5] = fma2(P0, w45.y, acc0[5]); acc1[5] = fma2(P1, w45.y, acc1[5]);
            acc0[6] = fma2(P0, w67.x, acc0[6]); acc1[6] = fma2(P1, w67.x, acc1[6]);
            acc0[7] = fma2(P0, w67.y, acc0[7]); acc1[7] = fma2(P1, w67.y, acc1[7]);
        }

        // Epilogue for this chunk
#pragma unroll
        for (int t = 0; t < 8; t++) {
            int q = hg * 8 + t;
            float2 w2v = W2S[q];
            float2 ai  = AiS[ii * EPP + q];
            float v0, v1, u0, u1;
            upk2(acc0[t], v0, v1);
            upk2(acc1[t], u0, u1);
            float2 bj0 = BjS[jl * EPP + q];
            float2 bj1 = BjS[(jl + 1) * EPP + q];
            sF0 = fmaf(fmaxf(v0 + ai.x + bj0.x, 0.f), w2v.x, sF0);
            sF0 = fmaf(fmaxf(v1 + ai.y + bj0.y, 0.f), w2v.y, sF0);
            sF1 = fmaf(fmaxf(u0 + ai.x + bj1.x, 0.f), w2v.x, sF1);
            sF1 = fmaf(fmaxf(u1 + ai.y + bj1.y, 0.f), w2v.y, sF1);
            if (mirror) {
                float2 bi  = BiS[ii * EPP + q];
                float2 aj0 = AjS[jl * EPP + q];
                float2 aj1 = AjS[(jl + 1) * EPP + q];
                sR0 = fmaf(fmaxf(v0 + aj0.x + bi.x, 0.f), w2v.x, sR0);
                sR0 = fmaf(fmaxf(v1 + aj0.y + bi.y, 0.f), w2v.y, sR0);
                sR1 = fmaf(fmaxf(u0 + aj1.x + bi.x, 0.f), w2v.x, sR1);
                sR1 = fmaf(fmaxf(u1 + aj1.y + bi.y, 0.f), w2v.y, sR1);
            }
        }
    }

    // Reduce over hg (lane bit 0)
    sF0 += __shfl_xor_sync(0xffffffffu, sF0, 1);
    sF1 += __shfl_xor_sync(0xffffffffu, sF1, 1);
    sR0 += __shfl_xor_sync(0xffffffffu, sR0, 1);
    sR1 += __shfl_xor_sync(0xffffffffu, sR1, 1);

    if (hg == 0) {
        const int ig = i0 + ii;
        g_scores[(brow + ig) * NN + j0 + jl]     = sF0;
        g_scores[(brow + ig) * NN + j0 + jl + 1] = sF1;
        if (mirror) {
            g_scores[(brow + j0 + jl) * NN + ig]     = sR0;
            g_scores[(brow + j0 + jl + 1) * NN + ig] = sR1;
        }
    }
}

// ---------------------------------------------------------------------------
// Kernel 3: per-row top-K + outputs
// ---------------------------------------------------------------------------
__global__ void __launch_bounds__(256, 4)
topk_out_kernel(const float* __restrict__ s,
                const int* __restrict__ Kp,
                float* __restrict__ ctx_out,
                float* __restrict__ gate_out,
                float* __restrict__ w_out,
                int writeGW) {
    __shared__ float scoreArr[NN];
    __shared__ float flagArr[NN];
    __shared__ int selIdx[NN];

    const int tid = threadIdx.x;
    const int lane = tid & 31;
    const int warp = tid >> 5;
    const int row = blockIdx.x;
    const int b = row >> 8;

    int kv = 8;
    if (Kp) {
        int raw = *Kp;
        if (raw < 1 || raw > 100000) {
            float f = __int_as_float(raw);
            raw = (int)f;
        }
        kv = raw;
    }
    if (kv > NN) kv = NN;
    if (kv < 0) kv = 0;

    scoreArr[tid] = g_scores[row * NN + tid];
    flagArr[tid] = 0.f;
    __syncthreads();

    if (warp == 0) {
        float v[8];
#pragma unroll
        for (int m = 0; m < 8; m++) v[m] = scoreArr[lane + (m << 5)];
        for (int t = 0; t < kv; t++) {
            float bv = v[0];
            int bm = 0;
#pragma unroll
            for (int m = 1; m < 8; m++)
                if (v[m] > bv) { bv = v[m]; bm = m; }
            int bi = lane + (bm << 5);
#pragma unroll
            for (int off = 16; off > 0; off >>= 1) {
                float ov = __shfl_xor_sync(0xffffffffu, bv, off);
                int   oi = __shfl_xor_sync(0xffffffffu, bi, off);
                if (ov > bv || (ov == bv && oi < bi)) { bv = ov; bi = oi; }
            }
            if (lane == (bi & 31)) v[bi >> 5] = -CUDART_INF_F;
            if (lane == 0) { selIdx[t] = bi; flagArr[bi] = 1.f; }
            __syncwarp();
        }
    }
    __syncthreads();

    float invK = (kv > 0) ? (1.f / (float)kv) : 0.f;
    if (writeGW) {
        float g = flagArr[tid];
        gate_out[row * NN + tid] = g;
        w_out[row * NN + tid] = g * invK;
    }
    if (tid < DD) {
        float a = 0.f;
        for (int t = 0; t < kv; t++) a += s[((b << 8) + selIdx[t]) * DD + tid];
        ctx_out[row * DD + tid] = a * invK;
    }
}

// ---------------------------------------------------------------------------
extern "C" void kernel_launch(void* const* d_in, const int* in_sizes, int n_in,
                              void* d_out, int out_size) {
    const float* s  = (const float*)d_in[0];
    const float* W1 = (const float*)d_in[1];
    const float* b1 = (const float*)d_in[2];
    const float* W2 = (const float*)d_in[3];
    const int* Kp = (n_in > 5) ? (const int*)d_in[5] : nullptr;

    const int n_ctx  = BN * DD;
    const int n_gate = BN * NN;
    float* ctx  = (float*)d_out;
    float* gate = ctx + n_ctx;
    float* wout = gate + n_gate;
    int writeGW = (out_size >= n_ctx + 2 * n_gate) ? 1 : 0;

    const int smem_bytes = SM2_TOTAL * (int)sizeof(float2);
    cudaFuncSetAttribute(score_tiles_kernel,
                         cudaFuncAttributeMaxDynamicSharedMemorySize, smem_bytes);

    precompute_AB_kernel<<<BN / 8, 256>>>(s, W1, b1);
    score_tiles_kernel<<<BB * NPAIRT, 256, smem_bytes>>>(s, W1, W2);
    topk_out_kernel<<<BN, 256>>>(s, Kp, ctx, gate, wout, writeGW);
}